// round 2
// baseline (speedup 1.0000x reference)
#include <cuda_runtime.h>

// Problem constants
#define EPSV 0.007f
#define NB   32     // batch
#define CI   128    // in channels
#define HI   56
#define WI   56
#define CO   256    // out channels (both stages)
#define HO   28
#define WO   28
#define C2   256    // stage-B in channels

// ---------------- scratch (static device memory; no allocations) ----------
__device__ float g_y[(size_t)NB * CO * HO * WO];        // YAT output, 25.7 MB
__device__ float g_wyat_t[CI * 9 * CO];                 // [ (ci*9+tap) ][ co ]
__device__ float g_wlin_t[C2 * 9 * CO];
__device__ float g_wsh_t[CI * CO];
__device__ float g_wsq[CO];

// ---------------- weight prep (transpose for coalesced smem fills) --------
__global__ void prep_yat(const float* __restrict__ w) {
    int k  = blockIdx.x;        // 0..1151  (ci*9+tap)
    int co = threadIdx.x;       // 0..255
    g_wyat_t[k * CO + co] = w[co * 1152 + k];
}
__global__ void prep_lin(const float* __restrict__ w) {
    int k  = blockIdx.x;        // 0..2303
    int co = threadIdx.x;
    g_wlin_t[k * CO + co] = w[co * 2304 + k];
}
__global__ void prep_sh(const float* __restrict__ w) {
    int k  = blockIdx.x;        // 0..127
    int co = threadIdx.x;
    g_wsh_t[k * CO + co] = w[co * CI + k];
}
__global__ void prep_wsq(const float* __restrict__ w) {
    __shared__ float red[128];
    int co = blockIdx.x;
    float s = 0.f;
    for (int k = threadIdx.x; k < 1152; k += 128) {
        float v = w[co * 1152 + k];
        s += v * v;
    }
    red[threadIdx.x] = s;
    __syncthreads();
    for (int off = 64; off > 0; off >>= 1) {
        if (threadIdx.x < off) red[threadIdx.x] += red[threadIdx.x + off];
        __syncthreads();
    }
    if (threadIdx.x == 0) g_wsq[co] = red[0];
}

// ---------------- Stage A: YAT conv (stride-2 3x3) + fused 1x1 shortcut ---
// Block: 64 co x 2 output rows x 28 px. 128 threads.
// Thread: 4 co x 7 px x 1 row.
__global__ __launch_bounds__(128)
void yat_kernel(const float* __restrict__ x, const float* __restrict__ alpha,
                float* __restrict__ out_id) {
    __shared__ __align__(16) float xs[8][5][58];     // [ci][row][col+1pad]
    __shared__ __align__(16) float ws[8 * 9][64];    // [ci*9+tap][co]
    __shared__ __align__(16) float wsh[8][64];       // [ci][co]

    const int tid   = threadIdx.x;
    const int co_b  = blockIdx.x;   // 0..3   (64-co group)
    const int h_b   = blockIdx.y;   // 0..13  (2 output rows)
    const int n     = blockIdx.z;   // 0..31
    const int co_t  = tid & 15;             // 4 co each
    const int px_t  = (tid >> 4) & 3;       // 7 px each (pw = px_t + 4j)
    const int row_t = tid >> 6;             // output row h0+row_t

    float acc[28], ida[28], psq[7];
#pragma unroll
    for (int i = 0; i < 28; i++) { acc[i] = 0.f; ida[i] = 0.f; }
#pragma unroll
    for (int j = 0; j < 7; j++) psq[j] = 0.f;

    const float* xbase = x + (size_t)n * CI * HI * WI;
    const int gr0 = 4 * h_b - 1;    // first input row needed

    for (int ci0 = 0; ci0 < CI; ci0 += 8) {
        __syncthreads();
        // fill xs: 8 ci x 5 rows x 58 cols (zero-padded)
        for (int idx = tid; idx < 8 * 5 * 58; idx += 128) {
            int cc  = idx / 290;
            int rem = idx - cc * 290;
            int r   = rem / 58;
            int c   = rem - r * 58;
            int gr  = gr0 + r;
            int gc  = c - 1;
            float v = 0.f;
            if (gr >= 0 && gr < HI && gc >= 0 && gc < WI)
                v = xbase[((ci0 + cc) * HI + gr) * WI + gc];
            xs[cc][r][c] = v;
        }
        // fill ws (coalesced gmem, conflict-free STS)
        for (int idx = tid; idx < 8 * 9 * 64; idx += 128) {
            int rr = idx >> 6;
            int co = idx & 63;
            ws[rr][co] = g_wyat_t[(ci0 * 9 + rr) * CO + co_b * 64 + co];
        }
        // fill shortcut weights
        for (int idx = tid; idx < 8 * 64; idx += 128) {
            int cc = idx >> 6;
            int co = idx & 63;
            wsh[cc][co] = g_wsh_t[(ci0 + cc) * CO + co_b * 64 + co];
        }
        __syncthreads();

#pragma unroll
        for (int cc = 0; cc < 8; cc++) {
#pragma unroll
            for (int kh = 0; kh < 3; kh++) {
                const int r = 2 * row_t + kh;
#pragma unroll
                for (int kw = 0; kw < 3; kw++) {
                    float xv[7];
#pragma unroll
                    for (int j = 0; j < 7; j++)
                        xv[j] = xs[cc][r][2 * (px_t + 4 * j) + kw];
                    float4 w4 = *(const float4*)&ws[cc * 9 + kh * 3 + kw][co_t * 4];
#pragma unroll
                    for (int j = 0; j < 7; j++) {
                        acc[0 * 7 + j] += w4.x * xv[j];
                        acc[1 * 7 + j] += w4.y * xv[j];
                        acc[2 * 7 + j] += w4.z * xv[j];
                        acc[3 * 7 + j] += w4.w * xv[j];
                        psq[j] += xv[j] * xv[j];
                    }
                    if (kh == 1 && kw == 1) {      // center tap = 1x1 stride-2 shortcut
                        float4 s4 = *(const float4*)&wsh[cc][co_t * 4];
#pragma unroll
                        for (int j = 0; j < 7; j++) {
                            ida[0 * 7 + j] += s4.x * xv[j];
                            ida[1 * 7 + j] += s4.y * xv[j];
                            ida[2 * 7 + j] += s4.z * xv[j];
                            ida[3 * 7 + j] += s4.w * xv[j];
                        }
                    }
                }
            }
        }
    }

    // epilogue: y = scale * dot^2 / (|patch|^2 + |w|^2 - 2 dot + eps)
    const float scale = powf(16.0f / logf(257.0f), alpha[0]);
    const int h = 2 * h_b + row_t;
#pragma unroll
    for (int i = 0; i < 4; i++) {
        const int co = co_b * 64 + co_t * 4 + i;
        const float wq = g_wsq[co];
        const size_t base = (((size_t)n * CO + co) * HO + h) * WO;
#pragma unroll
        for (int j = 0; j < 7; j++) {
            const int pw = px_t + 4 * j;
            const float dot = acc[i * 7 + j];
            const float d = psq[j] + wq - 2.f * dot + EPSV;
            g_y[base + pw] = scale * dot * dot / d;
            out_id[base + pw] = ida[i * 7 + j];   // identity term, added in stage B
        }
    }
}

// ---------------- Stage B: 3x3 stride-1 conv over g_y, += identity -------
__global__ __launch_bounds__(128)
void lin_kernel(float* __restrict__ out) {
    __shared__ __align__(16) float ys[8][4][30];
    __shared__ __align__(16) float ws[8 * 9][64];

    const int tid   = threadIdx.x;
    const int co_b  = blockIdx.x;
    const int h_b   = blockIdx.y;
    const int n     = blockIdx.z;
    const int co_t  = tid & 15;
    const int px_t  = (tid >> 4) & 3;
    const int row_t = tid >> 6;

    float acc[28];
#pragma unroll
    for (int i = 0; i < 28; i++) acc[i] = 0.f;

    const int h0 = 2 * h_b;

    for (int ci0 = 0; ci0 < C2; ci0 += 8) {
        __syncthreads();
        for (int idx = tid; idx < 8 * 4 * 30; idx += 128) {
            int cc  = idx / 120;
            int rem = idx - cc * 120;
            int r   = rem / 30;
            int c   = rem - r * 30;
            int gr  = h0 - 1 + r;
            int gc  = c - 1;
            float v = 0.f;
            if (gr >= 0 && gr < HO && gc >= 0 && gc < WO)
                v = g_y[(((size_t)n * C2 + ci0 + cc) * HO + gr) * WO + gc];
            ys[cc][r][c] = v;
        }
        for (int idx = tid; idx < 8 * 9 * 64; idx += 128) {
            int rr = idx >> 6;
            int co = idx & 63;
            ws[rr][co] = g_wlin_t[(ci0 * 9 + rr) * CO + co_b * 64 + co];
        }
        __syncthreads();

#pragma unroll
        for (int cc = 0; cc < 8; cc++) {
#pragma unroll
            for (int kh = 0; kh < 3; kh++) {
                const int r = row_t + kh;
#pragma unroll
                for (int kw = 0; kw < 3; kw++) {
                    float4 w4 = *(const float4*)&ws[cc * 9 + kh * 3 + kw][co_t * 4];
#pragma unroll
                    for (int j = 0; j < 7; j++) {
                        float xv = ys[cc][r][px_t + 4 * j + kw];
                        acc[0 * 7 + j] += w4.x * xv;
                        acc[1 * 7 + j] += w4.y * xv;
                        acc[2 * 7 + j] += w4.z * xv;
                        acc[3 * 7 + j] += w4.w * xv;
                    }
                }
            }
        }
    }

    const int h = h0 + row_t;
#pragma unroll
    for (int i = 0; i < 4; i++) {
        const int co = co_b * 64 + co_t * 4 + i;
        const size_t base = (((size_t)n * CO + co) * HO + h) * WO;
#pragma unroll
        for (int j = 0; j < 7; j++) {
            const int pw = px_t + 4 * j;
            out[base + pw] = acc[i * 7 + j] + out[base + pw];  // += identity
        }
    }
}

// ---------------- launch ---------------------------------------------------
extern "C" void kernel_launch(void* const* d_in, const int* in_sizes, int n_in,
                              void* d_out, int out_size) {
    const float* x       = (const float*)d_in[0];
    const float* w_yat   = (const float*)d_in[1];
    const float* alpha   = (const float*)d_in[2];
    const float* w_lin   = (const float*)d_in[3];
    const float* w_short = (const float*)d_in[4];
    float* out = (float*)d_out;

    prep_yat<<<CI * 9, CO>>>(w_yat);
    prep_lin<<<C2 * 9, CO>>>(w_lin);
    prep_sh<<<CI, CO>>>(w_short);
    prep_wsq<<<CO, 128>>>(w_yat);

    dim3 grid(4, 14, NB);           // co-groups x row-pairs x batch
    yat_kernel<<<grid, 128>>>(x, alpha, out);
    lin_kernel<<<grid, 128>>>(out);
}